// round 1
// baseline (speedup 1.0000x reference)
#include <cuda_runtime.h>

#define NB 4
#define NQS 512
#define NKS 1024
#define DD 64

// Scratch: k stored transposed per batch (kT[b][d][j]) so the attention kernel's
// shared tile is d-major (conflict-free lane reads over j). q stored row-major.
__device__ __align__(16) float g_kT[NB * DD * NKS];
__device__ __align__(16) float g_q [NB * NQS * DD];

// ---------------------------------------------------------------------------
// MLP kernel: y = relu(x@W1 + b1)@W2 + b2 for both key path (4096 rows) and
// query path (2048 rows). Grid = 192 blocks: [0,128) key-path, [128,192) query.
// Block = 128 threads = 32 rows x 4 slices (16 outputs each).
// ---------------------------------------------------------------------------
__device__ __forceinline__ void mlp_layer(const float* __restrict__ in_row,
                                          const float* __restrict__ Ws, int sl,
                                          const float* __restrict__ bs,
                                          float4 acc[4])
{
#pragma unroll
    for (int g = 0; g < 4; g++) acc[g] = ((const float4*)bs)[sl * 4 + g];
    for (int din = 0; din < 64; din++) {
        float xv = in_row[din];
        const float4* wr = (const float4*)(Ws + din * 64) + sl * 4;
#pragma unroll
        for (int g = 0; g < 4; g++) {
            float4 wv = wr[g];
            acc[g].x = fmaf(xv, wv.x, acc[g].x);
            acc[g].y = fmaf(xv, wv.y, acc[g].y);
            acc[g].z = fmaf(xv, wv.z, acc[g].z);
            acc[g].w = fmaf(xv, wv.w, acc[g].w);
        }
    }
}

__global__ __launch_bounds__(128) void mlp_kernel(
    const float* __restrict__ x1, const float* __restrict__ x2,
    const float* __restrict__ Wk1, const float* __restrict__ bk1,
    const float* __restrict__ Wk2, const float* __restrict__ bk2,
    const float* __restrict__ Wq1, const float* __restrict__ bq1,
    const float* __restrict__ Wq2, const float* __restrict__ bq2)
{
    extern __shared__ float sm[];
    float* W1s = sm;             // 4096
    float* W2s = sm + 4096;      // 4096
    float* b1s = sm + 8192;      // 64
    float* b2s = sm + 8256;      // 64
    float* xs  = sm + 8320;      // 32*65 = 2080 (pad 65 -> conflict-free row reads)
    float* hs  = sm + 10400;     // 2080
    // total 12480 floats = 49920 bytes

    const int t = threadIdx.x;
    const bool keypath = blockIdx.x < 128;
    const float *x, *W1, *b1, *W2, *b2;
    int row0;
    if (keypath) { x = x1; W1 = Wk1; b1 = bk1; W2 = Wk2; b2 = bk2; row0 = blockIdx.x * 32; }
    else         { x = x2; W1 = Wq1; b1 = bq1; W2 = Wq2; b2 = bq2; row0 = (blockIdx.x - 128) * 32; }

    for (int idx = t; idx < 1024; idx += 128) {
        ((float4*)W1s)[idx] = ((const float4*)W1)[idx];
        ((float4*)W2s)[idx] = ((const float4*)W2)[idx];
    }
    if (t < 16) {
        ((float4*)b1s)[t] = ((const float4*)b1)[t];
        ((float4*)b2s)[t] = ((const float4*)b2)[t];
    }
    for (int idx = t; idx < 512; idx += 128) {
        int rr = idx >> 4, c = idx & 15;
        float4 v = ((const float4*)(x + (size_t)(row0 + rr) * DD))[c];
        xs[rr * 65 + c * 4 + 0] = v.x;
        xs[rr * 65 + c * 4 + 1] = v.y;
        xs[rr * 65 + c * 4 + 2] = v.z;
        xs[rr * 65 + c * 4 + 3] = v.w;
    }
    __syncthreads();

    const int row = t >> 2, sl = t & 3;

    float4 acc[4];
    mlp_layer(xs + row * 65, W1s, sl, b1s, acc);   // layer 1
#pragma unroll
    for (int g = 0; g < 4; g++) {
        hs[row * 65 + sl * 16 + g * 4 + 0] = fmaxf(acc[g].x, 0.f);
        hs[row * 65 + sl * 16 + g * 4 + 1] = fmaxf(acc[g].y, 0.f);
        hs[row * 65 + sl * 16 + g * 4 + 2] = fmaxf(acc[g].z, 0.f);
        hs[row * 65 + sl * 16 + g * 4 + 3] = fmaxf(acc[g].w, 0.f);
    }
    __syncthreads();                                // full h row needed below
    mlp_layer(hs + row * 65, W2s, sl, b2s, acc);   // layer 2 (no relu)

    const int rg = row0 + row;
    if (keypath) {
        const int b = rg >> 10, j = rg & 1023;
        float* o = g_kT + (size_t)b * DD * NKS + j;
#pragma unroll
        for (int g = 0; g < 4; g++) {
            o[(size_t)(sl * 16 + g * 4 + 0) * NKS] = acc[g].x;
            o[(size_t)(sl * 16 + g * 4 + 1) * NKS] = acc[g].y;
            o[(size_t)(sl * 16 + g * 4 + 2) * NKS] = acc[g].z;
            o[(size_t)(sl * 16 + g * 4 + 3) * NKS] = acc[g].w;
        }
    } else {
        float4* o = (float4*)(g_q + (size_t)rg * DD) + sl * 4;
#pragma unroll
        for (int g = 0; g < 4; g++) o[g] = acc[g];
    }
}

// ---------------------------------------------------------------------------
// Attention kernel: one block = (b, tile of 16 queries). 256 threads.
// Phase 1: logits S[16][1024] in smem (kT tiles d-major, 2q x 2j micro-tile).
// Phase 2: row softmax (16 threads/row).
// Phase 3: O = P @ r (r tiles in smem, 1q x 4d micro-tile, float4 P loads).
// ---------------------------------------------------------------------------
__global__ __launch_bounds__(256) void attn_kernel(
    const float* __restrict__ rv, float* __restrict__ out)
{
    extern __shared__ float sm[];
    float* S    = sm;                       // 16*1024 = 16384
    float* kb   = sm + 16384;               // 64*68 = 4352 (k tile / r tile)
    float* qT   = sm + 16384 + 4352;        // 64*16 = 1024 (q transposed)
    float* linv = sm + 16384 + 4352 + 1024; // 16
    // total 21776 floats = 87104 bytes

    const int b    = blockIdx.y;
    const int qt   = blockIdx.x;
    const int t    = threadIdx.x;
    const int lane = t & 31;
    const int w    = t >> 5;

    // stage q (transposed: qT[d][i])
    {
        int i = t >> 4, c = t & 15;
        float4 v = ((const float4*)(g_q + (size_t)(b * NQS + qt * 16 + i) * DD))[c];
        qT[(c * 4 + 0) * 16 + i] = v.x;
        qT[(c * 4 + 1) * 16 + i] = v.y;
        qT[(c * 4 + 2) * 16 + i] = v.z;
        qT[(c * 4 + 3) * 16 + i] = v.w;
    }
    __syncthreads();

    const float* kTg = g_kT + (size_t)b * DD * NKS;
    const int i0 = w * 2;

    // -------- Phase 1: logits --------
    for (int kt = 0; kt < 16; kt++) {
        {   // load kT tile: rows d 0..63, cols [kt*64, kt*64+64)
            int d = t >> 2, c4 = t & 3;
            const float4* src = (const float4*)(kTg + (size_t)d * NKS + kt * 64 + c4 * 16);
            float4* dst = (float4*)(kb + d * 68 + c4 * 16);
#pragma unroll
            for (int c = 0; c < 4; c++) dst[c] = src[c];
        }
        __syncthreads();
        float s00 = 0.f, s01 = 0.f, s10 = 0.f, s11 = 0.f;
#pragma unroll 8
        for (int d = 0; d < 64; d++) {
            float2 kv = *(const float2*)(kb + d * 68 + 2 * lane);  // conflict-free
            float2 qv = *(const float2*)(qT + d * 16 + i0);        // broadcast
            s00 += fabsf(kv.x - qv.x);
            s01 += fabsf(kv.y - qv.x);
            s10 += fabsf(kv.x - qv.y);
            s11 += fabsf(kv.y - qv.y);
        }
        *(float2*)(S + (size_t)i0 * NKS + kt * 64 + 2 * lane)       = make_float2(-s00, -s01);
        *(float2*)(S + (size_t)(i0 + 1) * NKS + kt * 64 + 2 * lane) = make_float2(-s10, -s11);
        __syncthreads();
    }

    // -------- Phase 2: softmax over keys --------
    {
        int i = t >> 4, l16 = t & 15;
        float* Si = S + (size_t)i * NKS;
        float m = -3.0e38f;
        for (int j = l16; j < NKS; j += 16) m = fmaxf(m, Si[j]);
#pragma unroll
        for (int o = 8; o; o >>= 1) m = fmaxf(m, __shfl_xor_sync(0xffffffffu, m, o));
        float sum = 0.f;
        for (int j = l16; j < NKS; j += 16) {
            float p = __expf(Si[j] - m);
            Si[j] = p;
            sum += p;
        }
#pragma unroll
        for (int o = 8; o; o >>= 1) sum += __shfl_xor_sync(0xffffffffu, sum, o);
        if (l16 == 0) linv[i] = 1.0f / sum;
    }
    __syncthreads();

    // -------- Phase 3: O = P @ r --------
    const int i  = t >> 4;
    const int dg = t & 15;
    const float* Si = S + (size_t)i * NKS;
    const float* rg = rv + (size_t)b * NKS * DD;
    float a0 = 0.f, a1 = 0.f, a2 = 0.f, a3 = 0.f;

    for (int kt = 0; kt < 16; kt++) {
        {   // load r tile: rows k, 64 floats each -> kb[k][d] (pad 68)
            int rr = t >> 2, c4 = t & 3;
            const float4* src = (const float4*)(rg + (size_t)(kt * 64 + rr) * DD + c4 * 16);
            float4* dst = (float4*)(kb + rr * 68 + c4 * 16);
#pragma unroll
            for (int c = 0; c < 4; c++) dst[c] = src[c];
        }
        __syncthreads();
#pragma unroll 4
        for (int k = 0; k < 64; k += 4) {
            float4 p  = *(const float4*)(Si + kt * 64 + k);
            float4 r0 = *(const float4*)(kb + (k + 0) * 68 + dg * 4);
            float4 r1 = *(const float4*)(kb + (k + 1) * 68 + dg * 4);
            float4 r2 = *(const float4*)(kb + (k + 2) * 68 + dg * 4);
            float4 r3 = *(const float4*)(kb + (k + 3) * 68 + dg * 4);
            a0 = fmaf(p.x, r0.x, a0); a1 = fmaf(p.x, r0.y, a1);
            a2 = fmaf(p.x, r0.z, a2); a3 = fmaf(p.x, r0.w, a3);
            a0 = fmaf(p.y, r1.x, a0); a1 = fmaf(p.y, r1.y, a1);
            a2 = fmaf(p.y, r1.z, a2); a3 = fmaf(p.y, r1.w, a3);
            a0 = fmaf(p.z, r2.x, a0); a1 = fmaf(p.z, r2.y, a1);
            a2 = fmaf(p.z, r2.z, a2); a3 = fmaf(p.z, r2.w, a3);
            a0 = fmaf(p.w, r3.x, a0); a1 = fmaf(p.w, r3.y, a1);
            a2 = fmaf(p.w, r3.z, a2); a3 = fmaf(p.w, r3.w, a3);
        }
        __syncthreads();
    }

    const float li = linv[i];
    float4 o = make_float4(a0 * li, a1 * li, a2 * li, a3 * li);
    ((float4*)(out + (size_t)(b * NQS + qt * 16 + i) * DD))[dg] = o;
}

// ---------------------------------------------------------------------------
extern "C" void kernel_launch(void* const* d_in, const int* in_sizes, int n_in,
                              void* d_out, int out_size)
{
    const float* x1  = (const float*)d_in[0];
    const float* x2  = (const float*)d_in[1];
    const float* r   = (const float*)d_in[2];
    const float* Wk1 = (const float*)d_in[3];
    const float* bk1 = (const float*)d_in[4];
    const float* Wk2 = (const float*)d_in[5];
    const float* bk2 = (const float*)d_in[6];
    const float* Wq1 = (const float*)d_in[7];
    const float* bq1 = (const float*)d_in[8];
    const float* Wq2 = (const float*)d_in[9];
    const float* bq2 = (const float*)d_in[10];
    float* out = (float*)d_out;

    cudaFuncSetAttribute(mlp_kernel,  cudaFuncAttributeMaxDynamicSharedMemorySize, 50176);
    cudaFuncSetAttribute(attn_kernel, cudaFuncAttributeMaxDynamicSharedMemorySize, 87168);

    mlp_kernel<<<192, 128, 49920>>>(x1, x2, Wk1, bk1, Wk2, bk2, Wq1, bq1, Wq2, bq2);
    attn_kernel<<<dim3(32, 4), 256, 87104>>>(r, out);
}

// round 2
// speedup vs baseline: 1.4585x; 1.4585x over previous
#include <cuda_runtime.h>

#define NB 4
#define NQS 512
#define NKS 1024
#define DD 64

#define S_STRIDE 1025
#define S_FLOATS 8208            // 8*1025 = 8200, padded to 16B multiple
#define KB_FLOATS 8704           // max(64*132, 128*68)
#define KB_OFF   S_FLOATS
#define QT_OFF   (KB_OFF + KB_FLOATS)      // 16912
#define LINV_OFF (QT_OFF + 512)            // 17424
#define SMEM_FLOATS (LINV_OFF + 8)         // 17432 -> 69728 B

// Scratch: k transposed per batch (kT[b][d][j]); q row-major.
__device__ __align__(16) float g_kT[NB * DD * NKS];
__device__ __align__(16) float g_q [NB * NQS * DD];

// ---------------------------------------------------------------------------
// MLP kernel: 16 rows per block, 128 threads = 16 rows x 8 slices (8 outs each)
// Grid 384: blocks [0,256) key path (4096 rows), [256,384) query path (2048).
// ---------------------------------------------------------------------------
__device__ __forceinline__ void mlp_layer(const float* __restrict__ in_row,
                                          const float* __restrict__ Ws, int sl,
                                          const float* __restrict__ bs,
                                          float4 acc[2])
{
    acc[0] = ((const float4*)bs)[sl * 2 + 0];
    acc[1] = ((const float4*)bs)[sl * 2 + 1];
#pragma unroll 4
    for (int din = 0; din < 64; din++) {
        float xv = in_row[din];
        const float4* wr = (const float4*)(Ws + din * 64) + sl * 2;
        float4 w0 = wr[0], w1 = wr[1];
        acc[0].x = fmaf(xv, w0.x, acc[0].x);
        acc[0].y = fmaf(xv, w0.y, acc[0].y);
        acc[0].z = fmaf(xv, w0.z, acc[0].z);
        acc[0].w = fmaf(xv, w0.w, acc[0].w);
        acc[1].x = fmaf(xv, w1.x, acc[1].x);
        acc[1].y = fmaf(xv, w1.y, acc[1].y);
        acc[1].z = fmaf(xv, w1.z, acc[1].z);
        acc[1].w = fmaf(xv, w1.w, acc[1].w);
    }
}

__global__ __launch_bounds__(128) void mlp_kernel(
    const float* __restrict__ x1, const float* __restrict__ x2,
    const float* __restrict__ Wk1, const float* __restrict__ bk1,
    const float* __restrict__ Wk2, const float* __restrict__ bk2,
    const float* __restrict__ Wq1, const float* __restrict__ bq1,
    const float* __restrict__ Wq2, const float* __restrict__ bq2)
{
    extern __shared__ float sm[];
    float* W1s = sm;             // 4096
    float* W2s = sm + 4096;      // 4096
    float* b1s = sm + 8192;      // 64
    float* b2s = sm + 8256;      // 64
    float* xs  = sm + 8320;      // 16*65 = 1040
    float* hs  = sm + 9360;      // 1040
    // total 10400 floats = 41600 B

    const int t = threadIdx.x;
    const bool keypath = blockIdx.x < 256;
    const float *x, *W1, *b1, *W2, *b2;
    int row0;
    if (keypath) { x = x1; W1 = Wk1; b1 = bk1; W2 = Wk2; b2 = bk2; row0 = blockIdx.x * 16; }
    else         { x = x2; W1 = Wq1; b1 = bq1; W2 = Wq2; b2 = bq2; row0 = (blockIdx.x - 256) * 16; }

    for (int idx = t; idx < 1024; idx += 128) {
        ((float4*)W1s)[idx] = ((const float4*)W1)[idx];
        ((float4*)W2s)[idx] = ((const float4*)W2)[idx];
    }
    if (t < 16) {
        ((float4*)b1s)[t] = ((const float4*)b1)[t];
        ((float4*)b2s)[t] = ((const float4*)b2)[t];
    }
#pragma unroll
    for (int u = t; u < 256; u += 128) {
        int rr = u >> 4, c = u & 15;
        float4 v = ((const float4*)(x + (size_t)(row0 + rr) * DD))[c];
        xs[rr * 65 + c * 4 + 0] = v.x;
        xs[rr * 65 + c * 4 + 1] = v.y;
        xs[rr * 65 + c * 4 + 2] = v.z;
        xs[rr * 65 + c * 4 + 3] = v.w;
    }
    __syncthreads();

    const int row = t >> 3, sl = t & 7;

    float4 acc[2];
    mlp_layer(xs + row * 65, W1s, sl, b1s, acc);   // layer 1
    {
        float* h = hs + row * 65 + sl * 8;
        h[0] = fmaxf(acc[0].x, 0.f); h[1] = fmaxf(acc[0].y, 0.f);
        h[2] = fmaxf(acc[0].z, 0.f); h[3] = fmaxf(acc[0].w, 0.f);
        h[4] = fmaxf(acc[1].x, 0.f); h[5] = fmaxf(acc[1].y, 0.f);
        h[6] = fmaxf(acc[1].z, 0.f); h[7] = fmaxf(acc[1].w, 0.f);
    }
    __syncthreads();
    mlp_layer(hs + row * 65, W2s, sl, b2s, acc);   // layer 2 (no relu)

    const int rg = row0 + row;
    if (keypath) {
        const int b = rg >> 10, j = rg & 1023;
        float* o = g_kT + (size_t)b * DD * NKS + j;
        const float v[8] = {acc[0].x, acc[0].y, acc[0].z, acc[0].w,
                            acc[1].x, acc[1].y, acc[1].z, acc[1].w};
#pragma unroll
        for (int e = 0; e < 8; e++) o[(size_t)(sl * 8 + e) * NKS] = v[e];
    } else {
        float4* o = (float4*)(g_q + (size_t)rg * DD) + sl * 2;
        o[0] = acc[0]; o[1] = acc[1];
    }
}

// ---------------------------------------------------------------------------
// Attention kernel: one block = (b, tile of 8 queries), 256 threads, grid 64x4.
// Phase 1: logits over 128-key tiles, 4q x 1j micro-tile per thread.
// Phase 2: warp-per-row softmax.
// Phase 3: O = P @ r, 2q x 4d micro-tile, 4-way K-split + smem reduction.
// ---------------------------------------------------------------------------
__global__ __launch_bounds__(256) void attn_kernel(
    const float* __restrict__ rv, float* __restrict__ out)
{
    extern __shared__ float sm[];
    float* S    = sm;              // 8 rows, stride 1025
    float* kb   = sm + KB_OFF;     // phase1: [64][132] kT tile; phase3: [128][68] r tile
    float* qT   = sm + QT_OFF;     // [64][8] q transposed
    float* linv = sm + LINV_OFF;   // 8

    const int b    = blockIdx.y;
    const int qt   = blockIdx.x;
    const int t    = threadIdx.x;
    const int lane = t & 31;
    const int w    = t >> 5;

    // stage q transposed: qT[d][i]
    if (t < 128) {
        int i = t >> 4, c = t & 15;
        float4 v = ((const float4*)(g_q + (size_t)(b * NQS + qt * 8 + i) * DD))[c];
        qT[(c * 4 + 0) * 8 + i] = v.x;
        qT[(c * 4 + 1) * 8 + i] = v.y;
        qT[(c * 4 + 2) * 8 + i] = v.z;
        qT[(c * 4 + 3) * 8 + i] = v.w;
    }

    const float* kTg = g_kT + (size_t)b * DD * NKS;

    // -------- Phase 1: logits (8 tiles of 128 keys) --------
    {
        const int qg = w & 1;           // 2 groups of 4 queries
        const int jb = (w >> 1) * 32 + lane;  // 4 groups of 32 keys
        const float* qp = qT + qg * 4;

        for (int kt = 0; kt < 8; kt++) {
            __syncthreads();
            // stage kT tile: kb[d][132], 64 d x 128 j
#pragma unroll
            for (int u = t; u < 2048; u += 256) {
                int d = u >> 5, c = u & 31;
                *(float4*)(kb + d * 132 + c * 4) =
                    *(const float4*)(kTg + (size_t)d * NKS + kt * 128 + c * 4);
            }
            __syncthreads();

            float s0 = 0.f, s1 = 0.f, s2 = 0.f, s3 = 0.f;
            const float* kp = kb + jb;
#pragma unroll 8
            for (int d = 0; d < 64; d++) {
                float  kvv = kp[d * 132];
                float4 qv  = *(const float4*)(qp + d * 8);
                s0 += fabsf(kvv - qv.x);
                s1 += fabsf(kvv - qv.y);
                s2 += fabsf(kvv - qv.z);
                s3 += fabsf(kvv - qv.w);
            }
            const int col = kt * 128 + jb;
            S[(qg * 4 + 0) * S_STRIDE + col] = -s0;
            S[(qg * 4 + 1) * S_STRIDE + col] = -s1;
            S[(qg * 4 + 2) * S_STRIDE + col] = -s2;
            S[(qg * 4 + 3) * S_STRIDE + col] = -s3;
        }
    }
    __syncthreads();

    // -------- Phase 2: softmax, warp w owns row w --------
    {
        float* Srow = S + w * S_STRIDE;
        float m = -3.0e38f;
#pragma unroll 4
        for (int j = lane; j < NKS; j += 32) m = fmaxf(m, Srow[j]);
#pragma unroll
        for (int o = 16; o; o >>= 1) m = fmaxf(m, __shfl_xor_sync(0xffffffffu, m, o));
        float sum = 0.f;
#pragma unroll 4
        for (int j = lane; j < NKS; j += 32) {
            float p = __expf(Srow[j] - m);
            Srow[j] = p;
            sum += p;
        }
#pragma unroll
        for (int o = 16; o; o >>= 1) sum += __shfl_xor_sync(0xffffffffu, sum, o);
        if (lane == 0) linv[w] = 1.0f / sum;
    }

    // -------- Phase 3: O = P @ r, 2q x 4d per thread, 4-way K split --------
    const int kg = t >> 6;          // 0..3  (K split within tile)
    const int qg = (t >> 4) & 3;    // 0..3  (pairs of queries)
    const int dg = t & 15;          // 0..15 (float4 of output dims)
    const int q0 = qg * 2, q1 = q0 + 1;
    const float* rg = rv + (size_t)b * NKS * DD;

    float4 a0 = make_float4(0.f, 0.f, 0.f, 0.f);
    float4 a1 = make_float4(0.f, 0.f, 0.f, 0.f);

    for (int kt = 0; kt < 8; kt++) {
        __syncthreads();
        // stage r tile: kb[128][68]
#pragma unroll
        for (int u = t; u < 2048; u += 256) {
            int rr = u >> 4, c = u & 15;
            *(float4*)(kb + rr * 68 + c * 4) =
                *(const float4*)(rg + (size_t)(kt * 128 + rr) * DD + c * 4);
        }
        __syncthreads();

        const float* S0 = S + q0 * S_STRIDE + kt * 128 + kg * 32;
        const float* S1 = S + q1 * S_STRIDE + kt * 128 + kg * 32;
        const float* rb = kb + kg * 32 * 68 + dg * 4;
#pragma unroll 4
        for (int kk = 0; kk < 32; kk++) {
            float  p0 = S0[kk];
            float  p1 = S1[kk];
            float4 rv4 = *(const float4*)(rb + kk * 68);
            a0.x = fmaf(p0, rv4.x, a0.x);
            a0.y = fmaf(p0, rv4.y, a0.y);
            a0.z = fmaf(p0, rv4.z, a0.z);
            a0.w = fmaf(p0, rv4.w, a0.w);
            a1.x = fmaf(p1, rv4.x, a1.x);
            a1.y = fmaf(p1, rv4.y, a1.y);
            a1.z = fmaf(p1, rv4.z, a1.z);
            a1.w = fmaf(p1, rv4.w, a1.w);
        }
    }
    __syncthreads();

    // partial reduction across the 4 K-groups via smem (reuse kb)
    float4* kb4 = (float4*)kb;
    kb4[kg * 128 + q0 * 16 + dg] = a0;
    kb4[kg * 128 + q1 * 16 + dg] = a1;
    __syncthreads();

    if (t < 128) {
        const int q = t >> 4, dd = t & 15;
        float4 s = kb4[q * 16 + dd];
#pragma unroll
        for (int g = 1; g < 4; g++) {
            float4 v = kb4[g * 128 + q * 16 + dd];
            s.x += v.x; s.y += v.y; s.z += v.z; s.w += v.w;
        }
        const float li = linv[q];
        s.x *= li; s.y *= li; s.z *= li; s.w *= li;
        ((float4*)(out + (size_t)(b * NQS + qt * 8 + q) * DD))[dd] = s;
    }
}

// ---------------------------------------------------------------------------
extern "C" void kernel_launch(void* const* d_in, const int* in_sizes, int n_in,
                              void* d_out, int out_size)
{
    const float* x1  = (const float*)d_in[0];
    const float* x2  = (const float*)d_in[1];
    const float* r   = (const float*)d_in[2];
    const float* Wk1 = (const float*)d_in[3];
    const float* bk1 = (const float*)d_in[4];
    const float* Wk2 = (const float*)d_in[5];
    const float* bk2 = (const float*)d_in[6];
    const float* Wq1 = (const float*)d_in[7];
    const float* bq1 = (const float*)d_in[8];
    const float* Wq2 = (const float*)d_in[9];
    const float* bq2 = (const float*)d_in[10];
    float* out = (float*)d_out;

    cudaFuncSetAttribute(mlp_kernel,  cudaFuncAttributeMaxDynamicSharedMemorySize, 41600);
    cudaFuncSetAttribute(attn_kernel, cudaFuncAttributeMaxDynamicSharedMemorySize, SMEM_FLOATS * 4);

    mlp_kernel<<<384, 128, 41600>>>(x1, x2, Wk1, bk1, Wk2, bk2, Wq1, bq1, Wq2, bq2);
    attn_kernel<<<dim3(64, 4), 256, SMEM_FLOATS * 4>>>(r, out);
}

// round 3
// speedup vs baseline: 1.5980x; 1.0957x over previous
#include <cuda_runtime.h>

#define NB 4
#define NQS 512
#define NKS 1024
#define DD 64

typedef unsigned long long ull;

#define ADD2(o,a,b)   asm("add.rn.f32x2 %0, %1, %2;" : "=l"(o) : "l"(a), "l"(b))
#define FMA2(o,a,b,c) asm("fma.rn.f32x2 %0, %1, %2, %3;" : "=l"(o) : "l"(a), "l"(b), "l"(c))
#define ABSM 0x7FFFFFFF7FFFFFFFULL

// smem layout (floats) for attn kernel
#define S_STRIDE 1032
#define S_OFF    0                       // 4*1032 = 4128 (logits; later aliased as RED)
#define PD_STRIDE 2056
#define PD_OFF   4128                    // 4*2056 = 8224 (duplicated P pairs)
#define QD_OFF   (PD_OFF + 8224)        // 12352: 64*8 negated+duplicated q
#define LINV_OFF (QD_OFF + 512)         // 12864
#define SMEM_FLOATS (LINV_OFF + 8)      // 12872 -> 51488 B

// Scratch: k transposed per batch (kT[b][d][j]); q row-major.
__device__ __align__(16) float g_kT[NB * DD * NKS];
__device__ __align__(16) float g_q [NB * NQS * DD];

// ---------------------------------------------------------------------------
// MLP kernel (unchanged from R2): 16 rows/block, 128 thr = 16 rows x 8 slices.
// Grid 384: [0,256) key path, [256,384) query path.
// ---------------------------------------------------------------------------
__device__ __forceinline__ void mlp_layer(const float* __restrict__ in_row,
                                          const float* __restrict__ Ws, int sl,
                                          const float* __restrict__ bs,
                                          float4 acc[2])
{
    acc[0] = ((const float4*)bs)[sl * 2 + 0];
    acc[1] = ((const float4*)bs)[sl * 2 + 1];
#pragma unroll 4
    for (int din = 0; din < 64; din++) {
        float xv = in_row[din];
        const float4* wr = (const float4*)(Ws + din * 64) + sl * 2;
        float4 w0 = wr[0], w1 = wr[1];
        acc[0].x = fmaf(xv, w0.x, acc[0].x);
        acc[0].y = fmaf(xv, w0.y, acc[0].y);
        acc[0].z = fmaf(xv, w0.z, acc[0].z);
        acc[0].w = fmaf(xv, w0.w, acc[0].w);
        acc[1].x = fmaf(xv, w1.x, acc[1].x);
        acc[1].y = fmaf(xv, w1.y, acc[1].y);
        acc[1].z = fmaf(xv, w1.z, acc[1].z);
        acc[1].w = fmaf(xv, w1.w, acc[1].w);
    }
}

__global__ __launch_bounds__(128) void mlp_kernel(
    const float* __restrict__ x1, const float* __restrict__ x2,
    const float* __restrict__ Wk1, const float* __restrict__ bk1,
    const float* __restrict__ Wk2, const float* __restrict__ bk2,
    const float* __restrict__ Wq1, const float* __restrict__ bq1,
    const float* __restrict__ Wq2, const float* __restrict__ bq2)
{
    extern __shared__ float sm[];
    float* W1s = sm;
    float* W2s = sm + 4096;
    float* b1s = sm + 8192;
    float* b2s = sm + 8256;
    float* xs  = sm + 8320;
    float* hs  = sm + 9360;

    const int t = threadIdx.x;
    const bool keypath = blockIdx.x < 256;
    const float *x, *W1, *b1, *W2, *b2;
    int row0;
    if (keypath) { x = x1; W1 = Wk1; b1 = bk1; W2 = Wk2; b2 = bk2; row0 = blockIdx.x * 16; }
    else         { x = x2; W1 = Wq1; b1 = bq1; W2 = Wq2; b2 = bq2; row0 = (blockIdx.x - 256) * 16; }

    for (int idx = t; idx < 1024; idx += 128) {
        ((float4*)W1s)[idx] = ((const float4*)W1)[idx];
        ((float4*)W2s)[idx] = ((const float4*)W2)[idx];
    }
    if (t < 16) {
        ((float4*)b1s)[t] = ((const float4*)b1)[t];
        ((float4*)b2s)[t] = ((const float4*)b2)[t];
    }
#pragma unroll
    for (int u = t; u < 256; u += 128) {
        int rr = u >> 4, c = u & 15;
        float4 v = ((const float4*)(x + (size_t)(row0 + rr) * DD))[c];
        xs[rr * 65 + c * 4 + 0] = v.x;
        xs[rr * 65 + c * 4 + 1] = v.y;
        xs[rr * 65 + c * 4 + 2] = v.z;
        xs[rr * 65 + c * 4 + 3] = v.w;
    }
    __syncthreads();

    const int row = t >> 3, sl = t & 7;

    float4 acc[2];
    mlp_layer(xs + row * 65, W1s, sl, b1s, acc);
    {
        float* h = hs + row * 65 + sl * 8;
        h[0] = fmaxf(acc[0].x, 0.f); h[1] = fmaxf(acc[0].y, 0.f);
        h[2] = fmaxf(acc[0].z, 0.f); h[3] = fmaxf(acc[0].w, 0.f);
        h[4] = fmaxf(acc[1].x, 0.f); h[5] = fmaxf(acc[1].y, 0.f);
        h[6] = fmaxf(acc[1].z, 0.f); h[7] = fmaxf(acc[1].w, 0.f);
    }
    __syncthreads();
    mlp_layer(hs + row * 65, W2s, sl, b2s, acc);

    const int rg = row0 + row;
    if (keypath) {
        const int b = rg >> 10, j = rg & 1023;
        float* o = g_kT + (size_t)b * DD * NKS + j;
        const float v[8] = {acc[0].x, acc[0].y, acc[0].z, acc[0].w,
                            acc[1].x, acc[1].y, acc[1].z, acc[1].w};
#pragma unroll
        for (int e = 0; e < 8; e++) o[(size_t)(sl * 8 + e) * NKS] = v[e];
    } else {
        float4* o = (float4*)(g_q + (size_t)rg * DD) + sl * 2;
        o[0] = acc[0]; o[1] = acc[1];
    }
}

// ---------------------------------------------------------------------------
// Attention: one block = (b, 4 queries), 256 thr, grid (128,4) = 512 CTAs.
// Phase 1: packed f32x2 Laplace logits, k direct from L2, 4q x 2j(packed)/thr.
// Phase 2: warp-per-row softmax -> duplicated P pairs in smem.
// Phase 3: FFMA2 P@r, r direct from L2, 8-way K-split + smem reduction.
// ---------------------------------------------------------------------------
__global__ __launch_bounds__(256, 4) void attn_kernel(
    const float* __restrict__ rv, float* __restrict__ out)
{
    extern __shared__ float sm[];
    float* S    = sm + S_OFF;      // [4][1032] logits (aliased later as RED)
    float* PD   = sm + PD_OFF;     // [4][2056] duplicated P pairs
    float* QD   = sm + QD_OFF;     // [64][8] (-q) duplicated pairs
    float* linv = sm + LINV_OFF;   // 4

    const int b    = blockIdx.y;
    const int qt   = blockIdx.x;
    const int t    = threadIdx.x;
    const int lane = t & 31;
    const int w    = t >> 5;

    // stage QD[d][2i..2i+1] = -q[i][d] (negated + duplicated)
    {
        const int d = t >> 2, i = t & 3;
        float v = g_q[(size_t)(b * NQS + qt * 4 + i) * DD + d];
        QD[d * 8 + 2 * i + 0] = -v;
        QD[d * 8 + 2 * i + 1] = -v;
    }
    __syncthreads();

    const float* kTg = g_kT + (size_t)b * DD * NKS;

    // -------- Phase 1: logits, packed over key pairs --------
#pragma unroll
    for (int sweep = 0; sweep < 2; sweep++) {
        const int j = sweep * 512 + w * 64 + 2 * lane;
        ull a0 = 0, a1 = 0, a2 = 0, a3 = 0;   // (0.f,0.f) packed
        const float* kp = kTg + j;
#pragma unroll 4
        for (int d = 0; d < 64; d++) {
            ull k2 = *(const ull*)(kp + (size_t)d * NKS);           // 2 keys
            ulonglong2 nq01 = *(const ulonglong2*)(QD + d * 8);     // (-q0,-q0),(-q1,-q1)
            ulonglong2 nq23 = *(const ulonglong2*)(QD + d * 8 + 4);
            ull t0, t1, t2, t3;
            ADD2(t0, k2, nq01.x); t0 &= ABSM; ADD2(a0, a0, t0);
            ADD2(t1, k2, nq01.y); t1 &= ABSM; ADD2(a1, a1, t1);
            ADD2(t2, k2, nq23.x); t2 &= ABSM; ADD2(a2, a2, t2);
            ADD2(t3, k2, nq23.y); t3 &= ABSM; ADD2(a3, a3, t3);
        }
#pragma unroll
        for (int q = 0; q < 4; q++) {
            ull a = (q == 0) ? a0 : (q == 1) ? a1 : (q == 2) ? a2 : a3;
            float lo = __uint_as_float((unsigned)a);
            float hi = __uint_as_float((unsigned)(a >> 32));
            *(float2*)(S + q * S_STRIDE + j) = make_float2(-lo, -hi);
        }
    }
    __syncthreads();

    // -------- Phase 2: softmax rows 0..3 on warps 0..3; write dup'd P --------
    if (w < 4) {
        const float* Srow = S + w * S_STRIDE;
        float* Prow = PD + w * PD_STRIDE;
        float m = -3.0e38f;
#pragma unroll 8
        for (int j = lane; j < NKS; j += 32) m = fmaxf(m, Srow[j]);
#pragma unroll
        for (int o = 16; o; o >>= 1) m = fmaxf(m, __shfl_xor_sync(0xffffffffu, m, o));
        float sum = 0.f;
#pragma unroll 8
        for (int j = lane; j < NKS; j += 32) {
            float p = __expf(Srow[j] - m);
            *(float2*)(Prow + 2 * j) = make_float2(p, p);
            sum += p;
        }
#pragma unroll
        for (int o = 16; o; o >>= 1) sum += __shfl_xor_sync(0xffffffffu, sum, o);
        if (lane == 0) linv[w] = 1.0f / sum;
    }
    __syncthreads();

    // -------- Phase 3: O = P @ r via FFMA2, 8-way K split --------
    const int kg = t >> 5;          // warp = K group (128 keys each)
    const int qg = (t >> 4) & 1;    // query pair
    const int dg = t & 15;          // float4 of output dims
    const float* rb  = rv + (size_t)b * NKS * DD + (size_t)kg * 128 * DD + dg * 4;
    const float* PD0 = PD + (qg * 2 + 0) * PD_STRIDE + kg * 256;
    const float* PD1 = PD + (qg * 2 + 1) * PD_STRIDE + kg * 256;

    ull aA0 = 0, aA1 = 0, aB0 = 0, aB1 = 0;   // q0:(d01,d23), q1:(d01,d23)
#pragma unroll 4
    for (int kk = 0; kk < 128; kk++) {
        ull p0 = *(const ull*)(PD0 + 2 * kk);                 // (p0,p0)
        ull p1 = *(const ull*)(PD1 + 2 * kk);                 // (p1,p1)
        ulonglong2 r2 = *(const ulonglong2*)(rb + (size_t)kk * DD);  // (r_d0,r_d1),(r_d2,r_d3)
        FMA2(aA0, p0, r2.x, aA0);
        FMA2(aA1, p0, r2.y, aA1);
        FMA2(aB0, p1, r2.x, aB0);
        FMA2(aB1, p1, r2.y, aB1);
    }

    // partials -> RED (aliases S region; S is dead after phase 2)
    float4* RED = (float4*)sm;
    {
        float4 vA = make_float4(__uint_as_float((unsigned)aA0),
                                __uint_as_float((unsigned)(aA0 >> 32)),
                                __uint_as_float((unsigned)aA1),
                                __uint_as_float((unsigned)(aA1 >> 32)));
        float4 vB = make_float4(__uint_as_float((unsigned)aB0),
                                __uint_as_float((unsigned)(aB0 >> 32)),
                                __uint_as_float((unsigned)aB1),
                                __uint_as_float((unsigned)(aB1 >> 32)));
        RED[kg * 64 + (qg * 2 + 0) * 16 + dg] = vA;
        RED[kg * 64 + (qg * 2 + 1) * 16 + dg] = vB;
    }
    __syncthreads();

    if (t < 64) {
        const int q = t >> 4, dd = t & 15;
        float4 s = RED[q * 16 + dd];
#pragma unroll
        for (int g = 1; g < 8; g++) {
            float4 v = RED[g * 64 + q * 16 + dd];
            s.x += v.x; s.y += v.y; s.z += v.z; s.w += v.w;
        }
        const float li = linv[q];
        s.x *= li; s.y *= li; s.z *= li; s.w *= li;
        ((float4*)(out + (size_t)(b * NQS + qt * 4 + q) * DD))[dd] = s;
    }
}

// ---------------------------------------------------------------------------
extern "C" void kernel_launch(void* const* d_in, const int* in_sizes, int n_in,
                              void* d_out, int out_size)
{
    const float* x1  = (const float*)d_in[0];
    const float* x2  = (const float*)d_in[1];
    const float* r   = (const float*)d_in[2];
    const float* Wk1 = (const float*)d_in[3];
    const float* bk1 = (const float*)d_in[4];
    const float* Wk2 = (const float*)d_in[5];
    const float* bk2 = (const float*)d_in[6];
    const float* Wq1 = (const float*)d_in[7];
    const float* bq1 = (const float*)d_in[8];
    const float* Wq2 = (const float*)d_in[9];
    const float* bq2 = (const float*)d_in[10];
    float* out = (float*)d_out;

    cudaFuncSetAttribute(mlp_kernel,  cudaFuncAttributeMaxDynamicSharedMemorySize, 41600);
    cudaFuncSetAttribute(attn_kernel, cudaFuncAttributeMaxDynamicSharedMemorySize, SMEM_FLOATS * 4);

    mlp_kernel<<<384, 128, 41600>>>(x1, x2, Wk1, bk1, Wk2, bk2, Wq1, bq1, Wq2, bq2);
    attn_kernel<<<dim3(128, 4), 256, SMEM_FLOATS * 4>>>(r, out);
}

// round 4
// speedup vs baseline: 1.6998x; 1.0637x over previous
#include <cuda_runtime.h>

#define NB 4
#define NQS 512
#define NKS 1024
#define DD 64

typedef unsigned long long ull;

#define ADD2(o,a,b)   asm("add.rn.f32x2 %0, %1, %2;" : "=l"(o) : "l"(a), "l"(b))
#define FMA2(o,a,b,c) asm("fma.rn.f32x2 %0, %1, %2, %3;" : "=l"(o) : "l"(a), "l"(b), "l"(c))
#define ABSM 0x7FFFFFFF7FFFFFFFULL

// smem layout (floats) for attn kernel
#define S_STRIDE 1032
#define S_OFF    0                       // 4*1032 = 4128 (logits; later aliased as RED)
#define PD_STRIDE 2056
#define PD_OFF   4128                    // 4*2056 = 8224 (duplicated P pairs)
#define QD_OFF   (PD_OFF + 8224)        // 12352: 64*8 negated+duplicated q
#define MP_OFF   (QD_OFF + 512)         // 12864: 8 max partials
#define SP_OFF   (MP_OFF + 8)           // 12872: 8 sum partials
#define SMEM_FLOATS (SP_OFF + 8)        // 12880 -> 51520 B

// Scratch: k transposed per batch (kT[b][d][j]); q row-major.
__device__ __align__(16) float g_kT[NB * DD * NKS];
__device__ __align__(16) float g_q [NB * NQS * DD];

// ---------------------------------------------------------------------------
// MLP kernel (unchanged): 16 rows/block, 128 thr = 16 rows x 8 slices.
// Grid 384: [0,256) key path, [256,384) query path.
// ---------------------------------------------------------------------------
__device__ __forceinline__ void mlp_layer(const float* __restrict__ in_row,
                                          const float* __restrict__ Ws, int sl,
                                          const float* __restrict__ bs,
                                          float4 acc[2])
{
    acc[0] = ((const float4*)bs)[sl * 2 + 0];
    acc[1] = ((const float4*)bs)[sl * 2 + 1];
#pragma unroll 4
    for (int din = 0; din < 64; din++) {
        float xv = in_row[din];
        const float4* wr = (const float4*)(Ws + din * 64) + sl * 2;
        float4 w0 = wr[0], w1 = wr[1];
        acc[0].x = fmaf(xv, w0.x, acc[0].x);
        acc[0].y = fmaf(xv, w0.y, acc[0].y);
        acc[0].z = fmaf(xv, w0.z, acc[0].z);
        acc[0].w = fmaf(xv, w0.w, acc[0].w);
        acc[1].x = fmaf(xv, w1.x, acc[1].x);
        acc[1].y = fmaf(xv, w1.y, acc[1].y);
        acc[1].z = fmaf(xv, w1.z, acc[1].z);
        acc[1].w = fmaf(xv, w1.w, acc[1].w);
    }
}

__global__ __launch_bounds__(128) void mlp_kernel(
    const float* __restrict__ x1, const float* __restrict__ x2,
    const float* __restrict__ Wk1, const float* __restrict__ bk1,
    const float* __restrict__ Wk2, const float* __restrict__ bk2,
    const float* __restrict__ Wq1, const float* __restrict__ bq1,
    const float* __restrict__ Wq2, const float* __restrict__ bq2)
{
    extern __shared__ float sm[];
    float* W1s = sm;
    float* W2s = sm + 4096;
    float* b1s = sm + 8192;
    float* b2s = sm + 8256;
    float* xs  = sm + 8320;
    float* hs  = sm + 9360;

    const int t = threadIdx.x;
    const bool keypath = blockIdx.x < 256;
    const float *x, *W1, *b1, *W2, *b2;
    int row0;
    if (keypath) { x = x1; W1 = Wk1; b1 = bk1; W2 = Wk2; b2 = bk2; row0 = blockIdx.x * 16; }
    else         { x = x2; W1 = Wq1; b1 = bq1; W2 = Wq2; b2 = bq2; row0 = (blockIdx.x - 256) * 16; }

    for (int idx = t; idx < 1024; idx += 128) {
        ((float4*)W1s)[idx] = ((const float4*)W1)[idx];
        ((float4*)W2s)[idx] = ((const float4*)W2)[idx];
    }
    if (t < 16) {
        ((float4*)b1s)[t] = ((const float4*)b1)[t];
        ((float4*)b2s)[t] = ((const float4*)b2)[t];
    }
#pragma unroll
    for (int u = t; u < 256; u += 128) {
        int rr = u >> 4, c = u & 15;
        float4 v = ((const float4*)(x + (size_t)(row0 + rr) * DD))[c];
        xs[rr * 65 + c * 4 + 0] = v.x;
        xs[rr * 65 + c * 4 + 1] = v.y;
        xs[rr * 65 + c * 4 + 2] = v.z;
        xs[rr * 65 + c * 4 + 3] = v.w;
    }
    __syncthreads();

    const int row = t >> 3, sl = t & 7;

    float4 acc[2];
    mlp_layer(xs + row * 65, W1s, sl, b1s, acc);
    {
        float* h = hs + row * 65 + sl * 8;
        h[0] = fmaxf(acc[0].x, 0.f); h[1] = fmaxf(acc[0].y, 0.f);
        h[2] = fmaxf(acc[0].z, 0.f); h[3] = fmaxf(acc[0].w, 0.f);
        h[4] = fmaxf(acc[1].x, 0.f); h[5] = fmaxf(acc[1].y, 0.f);
        h[6] = fmaxf(acc[1].z, 0.f); h[7] = fmaxf(acc[1].w, 0.f);
    }
    __syncthreads();
    mlp_layer(hs + row * 65, W2s, sl, b2s, acc);

    const int rg = row0 + row;
    if (keypath) {
        const int b = rg >> 10, j = rg & 1023;
        float* o = g_kT + (size_t)b * DD * NKS + j;
        const float v[8] = {acc[0].x, acc[0].y, acc[0].z, acc[0].w,
                            acc[1].x, acc[1].y, acc[1].z, acc[1].w};
#pragma unroll
        for (int e = 0; e < 8; e++) o[(size_t)(sl * 8 + e) * NKS] = v[e];
    } else {
        float4* o = (float4*)(g_q + (size_t)rg * DD) + sl * 2;
        o[0] = acc[0]; o[1] = acc[1];
    }
}

// ---------------------------------------------------------------------------
// Attention: one block = (b, 4 queries), 256 thr, grid (128,4) = 512 CTAs.
// Phase 1: packed f32x2 logits, 4q x 2 key-pairs/thread (2 indep LDG chains).
// Phase 2: softmax on 8 warps (2 per row), two-pass via smem partials.
// Phase 3: FFMA2 P@r, r direct from L2, 8-way K-split + smem reduction.
// ---------------------------------------------------------------------------
__global__ __launch_bounds__(256, 4) void attn_kernel(
    const float* __restrict__ rv, float* __restrict__ out)
{
    extern __shared__ float sm[];
    float* S    = sm + S_OFF;      // [4][1032] logits (aliased later as RED)
    float* PD   = sm + PD_OFF;     // [4][2056] duplicated P pairs
    float* QD   = sm + QD_OFF;     // [64][8] (-q) duplicated pairs
    float* Mp   = sm + MP_OFF;     // [4][2] max partials
    float* Sp   = sm + SP_OFF;     // [4][2] sum partials

    const int b    = blockIdx.y;
    const int qt   = blockIdx.x;
    const int t    = threadIdx.x;
    const int lane = t & 31;
    const int w    = t >> 5;

    // stage QD[d][2i..2i+1] = -q[i][d] (negated + duplicated)
    {
        const int d = t >> 2, i = t & 3;
        float v = g_q[(size_t)(b * NQS + qt * 4 + i) * DD + d];
        QD[d * 8 + 2 * i + 0] = -v;
        QD[d * 8 + 2 * i + 1] = -v;
    }
    __syncthreads();

    const float* kTg = g_kT + (size_t)b * DD * NKS;

    // -------- Phase 1: logits, 2 independent key-pair chains per thread ----
    {
        const int j0 = w * 64 + 2 * lane;   // keys [w*64, w*64+64)
        const int j1 = 512 + j0;            // keys [512+w*64, ...)
        const float* kp0 = kTg + j0;
        const float* kp1 = kTg + j1;

        ull a00 = 0, a01 = 0, a02 = 0, a03 = 0;   // chain A: 4 queries
        ull a10 = 0, a11 = 0, a12 = 0, a13 = 0;   // chain B: 4 queries
#pragma unroll 4
        for (int d = 0; d < 64; d++) {
            ull kA = *(const ull*)(kp0 + (size_t)d * NKS);
            ull kB = *(const ull*)(kp1 + (size_t)d * NKS);
            ulonglong2 nq01 = *(const ulonglong2*)(QD + d * 8);
            ulonglong2 nq23 = *(const ulonglong2*)(QD + d * 8 + 4);
            ull u;
            ADD2(u, kA, nq01.x); u &= ABSM; ADD2(a00, a00, u);
            ADD2(u, kA, nq01.y); u &= ABSM; ADD2(a01, a01, u);
            ADD2(u, kA, nq23.x); u &= ABSM; ADD2(a02, a02, u);
            ADD2(u, kA, nq23.y); u &= ABSM; ADD2(a03, a03, u);
            ADD2(u, kB, nq01.x); u &= ABSM; ADD2(a10, a10, u);
            ADD2(u, kB, nq01.y); u &= ABSM; ADD2(a11, a11, u);
            ADD2(u, kB, nq23.x); u &= ABSM; ADD2(a12, a12, u);
            ADD2(u, kB, nq23.y); u &= ABSM; ADD2(a13, a13, u);
        }
        const ull accA[4] = {a00, a01, a02, a03};
        const ull accB[4] = {a10, a11, a12, a13};
#pragma unroll
        for (int q = 0; q < 4; q++) {
            ull a = accA[q], bq = accB[q];
            *(float2*)(S + q * S_STRIDE + j0) =
                make_float2(-__uint_as_float((unsigned)a),
                            -__uint_as_float((unsigned)(a >> 32)));
            *(float2*)(S + q * S_STRIDE + j1) =
                make_float2(-__uint_as_float((unsigned)bq),
                            -__uint_as_float((unsigned)(bq >> 32)));
        }
    }
    __syncthreads();

    // -------- Phase 2: softmax, 2 warps per row (halves of 1024 keys) ------
    {
        const int row  = w >> 1;
        const int half = w & 1;
        const float* Srow = S + row * S_STRIDE + half * 512;
        float* Prow = PD + row * PD_STRIDE + half * 1024;

        float m = -3.0e38f;
#pragma unroll
        for (int it = 0; it < 16; it++) m = fmaxf(m, Srow[it * 32 + lane]);
#pragma unroll
        for (int o = 16; o; o >>= 1) m = fmaxf(m, __shfl_xor_sync(0xffffffffu, m, o));
        if (lane == 0) Mp[row * 2 + half] = m;
        __syncthreads();
        const float M = fmaxf(Mp[row * 2], Mp[row * 2 + 1]);

        float sum = 0.f;
#pragma unroll
        for (int it = 0; it < 16; it++) {
            float p = __expf(Srow[it * 32 + lane] - M);
            *(float2*)(Prow + 2 * (it * 32 + lane)) = make_float2(p, p);
            sum += p;
        }
#pragma unroll
        for (int o = 16; o; o >>= 1) sum += __shfl_xor_sync(0xffffffffu, sum, o);
        if (lane == 0) Sp[row * 2 + half] = sum;
    }
    __syncthreads();

    // -------- Phase 3: O = P @ r via FFMA2, 8-way K split ------------------
    const int kg = t >> 5;          // warp = K group (128 keys each)
    const int qg = (t >> 4) & 1;    // query pair
    const int dg = t & 15;          // float4 of output dims
    const float* rb  = rv + (size_t)b * NKS * DD + (size_t)kg * 128 * DD + dg * 4;
    const float* PD0 = PD + (qg * 2 + 0) * PD_STRIDE + kg * 256;
    const float* PD1 = PD + (qg * 2 + 1) * PD_STRIDE + kg * 256;

    ull aA0 = 0, aA1 = 0, aB0 = 0, aB1 = 0;
#pragma unroll 4
    for (int kk = 0; kk < 128; kk++) {
        ull p0 = *(const ull*)(PD0 + 2 * kk);
        ull p1 = *(const ull*)(PD1 + 2 * kk);
        ulonglong2 r2 = *(const ulonglong2*)(rb + (size_t)kk * DD);
        FMA2(aA0, p0, r2.x, aA0);
        FMA2(aA1, p0, r2.y, aA1);
        FMA2(aB0, p1, r2.x, aB0);
        FMA2(aB1, p1, r2.y, aB1);
    }

    // partials -> RED (aliases S region; S dead after phase 2)
    float4* RED = (float4*)sm;
    {
        float4 vA = make_float4(__uint_as_float((unsigned)aA0),
                                __uint_as_float((unsigned)(aA0 >> 32)),
                                __uint_as_float((unsigned)aA1),
                                __uint_as_float((unsigned)(aA1 >> 32)));
        float4 vB = make_float4(__uint_as_float((unsigned)aB0),
                                __uint_as_float((unsigned)(aB0 >> 32)),
                                __uint_as_float((unsigned)aB1),
                                __uint_as_float((unsigned)(aB1 >> 32)));
        RED[kg * 64 + (qg * 2 + 0) * 16 + dg] = vA;
        RED[kg * 64 + (qg * 2 + 1) * 16 + dg] = vB;
    }
    __syncthreads();

    if (t < 64) {
        const int q = t >> 4, dd = t & 15;
        float4 s = RED[q * 16 + dd];
#pragma unroll
        for (int g = 1; g < 8; g++) {
            float4 v = RED[g * 64 + q * 16 + dd];
            s.x += v.x; s.y += v.y; s.z += v.z; s.w += v.w;
        }
        const float li = 1.0f / (Sp[q * 2] + Sp[q * 2 + 1]);
        s.x *= li; s.y *= li; s.z *= li; s.w *= li;
        ((float4*)(out + (size_t)(b * NQS + qt * 4 + q) * DD))[dd] = s;
    }
}

// ---------------------------------------------------------------------------
extern "C" void kernel_launch(void* const* d_in, const int* in_sizes, int n_in,
                              void* d_out, int out_size)
{
    const float* x1  = (const float*)d_in[0];
    const float* x2  = (const float*)d_in[1];
    const float* r   = (const float*)d_in[2];
    const float* Wk1 = (const float*)d_in[3];
    const float* bk1 = (const float*)d_in[4];
    const float* Wk2 = (const float*)d_in[5];
    const float* bk2 = (const float*)d_in[6];
    const float* Wq1 = (const float*)d_in[7];
    const float* bq1 = (const float*)d_in[8];
    const float* Wq2 = (const float*)d_in[9];
    const float* bq2 = (const float*)d_in[10];
    float* out = (float*)d_out;

    cudaFuncSetAttribute(mlp_kernel,  cudaFuncAttributeMaxDynamicSharedMemorySize, 41600);
    cudaFuncSetAttribute(attn_kernel, cudaFuncAttributeMaxDynamicSharedMemorySize, SMEM_FLOATS * 4);

    mlp_kernel<<<384, 128, 41600>>>(x1, x2, Wk1, bk1, Wk2, bk2, Wq1, bq1, Wq2, bq2);
    attn_kernel<<<dim3(128, 4), 256, SMEM_FLOATS * 4>>>(r, out);
}